// round 1
// baseline (speedup 1.0000x reference)
#include <cuda_runtime.h>

#define HW    1560
#define TQ    2
#define QTOT  3120
#define KTOT  12480
#define HEADS 12
#define DH    128
#define DIM   1536

// ---------------- scratch (device globals; no allocation allowed) ----------------
__device__ float g_q[QTOT * DIM];     // 19.2 MB
__device__ float g_k[KTOT * DIM];     // 76.7 MB
__device__ float g_v[KTOT * DIM];     // 76.7 MB
__device__ float g_attn[QTOT * DIM];  // 19.2 MB

// ---------------- helpers ----------------
__device__ __forceinline__ unsigned f2tf(float f) {
    unsigned u;
    asm("cvt.rna.tf32.f32 %0, %1;" : "=r"(u) : "f"(f));
    return u;
}

__device__ __forceinline__ void mma_tf32(float* d, const unsigned* a, unsigned b0, unsigned b1) {
    asm volatile(
        "mma.sync.aligned.m16n8k8.row.col.f32.tf32.tf32.f32 "
        "{%0,%1,%2,%3}, {%4,%5,%6,%7}, {%8,%9}, {%0,%1,%2,%3};"
        : "+f"(d[0]), "+f"(d[1]), "+f"(d[2]), "+f"(d[3])
        : "r"(a[0]), "r"(a[1]), "r"(a[2]), "r"(a[3]), "r"(b0), "r"(b1));
}

// ---------------- GEMM: C[M,N] = A[M,K] @ W[N,K]^T + bias[N]  (tf32 mma) ----------------
// block tile 128x128x32, 256 threads = 8 warps (2 M x 4 N), warp tile 64x32
__global__ __launch_bounds__(256) void gemm_bias_tf32(
    const float* __restrict__ A, const float* __restrict__ W,
    const float* __restrict__ bias, float* __restrict__ C,
    int M, int N, int K)
{
    __shared__ unsigned As[128 * 36];  // [m][k], stride 36 -> bank = 4m+k, conflict-free
    __shared__ unsigned Ws[128 * 36];  // [n][k]

    const int tid  = threadIdx.x;
    const int warp = tid >> 5, lane = tid & 31;
    const int g = lane >> 2, t4 = lane & 3;
    const int wm = warp >> 2, wn = warp & 3;
    const int bm = blockIdx.y * 128, bn = blockIdx.x * 128;

    float acc[4][4][4] = {};

    const int lc = (tid & 7) * 4;  // col within 32-wide k tile (float4)
    const int lr = tid >> 3;       // base row (0..31), rows lr + 32*i

    float4 aF[4], wF[4];
    #pragma unroll
    for (int i = 0; i < 4; i++) {
        int row = lr + 32 * i;
        long ar = bm + row;
        aF[i] = (ar < M) ? *(const float4*)(A + ar * (long)K + lc)
                         : make_float4(0.f, 0.f, 0.f, 0.f);
        wF[i] = *(const float4*)(W + (long)(bn + row) * K + lc);
    }

    const int KT = K >> 5;
    for (int kt = 0; kt < KT; kt++) {
        #pragma unroll
        for (int i = 0; i < 4; i++) {
            int row = lr + 32 * i;
            *(uint4*)&As[row * 36 + lc] =
                make_uint4(f2tf(aF[i].x), f2tf(aF[i].y), f2tf(aF[i].z), f2tf(aF[i].w));
            *(uint4*)&Ws[row * 36 + lc] =
                make_uint4(f2tf(wF[i].x), f2tf(wF[i].y), f2tf(wF[i].z), f2tf(wF[i].w));
        }
        __syncthreads();

        if (kt + 1 < KT) {
            int k0 = (kt + 1) << 5;
            #pragma unroll
            for (int i = 0; i < 4; i++) {
                int row = lr + 32 * i;
                long ar = bm + row;
                aF[i] = (ar < M) ? *(const float4*)(A + ar * (long)K + k0 + lc)
                                 : make_float4(0.f, 0.f, 0.f, 0.f);
                wF[i] = *(const float4*)(W + (long)(bn + row) * K + k0 + lc);
            }
        }

        #pragma unroll
        for (int kk = 0; kk < 4; kk++) {
            const int kb = kk * 8;
            unsigned a[4][4];
            #pragma unroll
            for (int mt = 0; mt < 4; mt++) {
                int m = wm * 64 + mt * 16 + g;
                a[mt][0] = As[m * 36 + kb + t4];
                a[mt][1] = As[(m + 8) * 36 + kb + t4];
                a[mt][2] = As[m * 36 + kb + t4 + 4];
                a[mt][3] = As[(m + 8) * 36 + kb + t4 + 4];
            }
            #pragma unroll
            for (int nt = 0; nt < 4; nt++) {
                int n = wn * 32 + nt * 8 + g;
                unsigned b0 = Ws[n * 36 + kb + t4];
                unsigned b1 = Ws[n * 36 + kb + t4 + 4];
                #pragma unroll
                for (int mt = 0; mt < 4; mt++) mma_tf32(acc[mt][nt], a[mt], b0, b1);
            }
        }
        __syncthreads();
    }

    #pragma unroll
    for (int mt = 0; mt < 4; mt++) {
        int r = bm + wm * 64 + mt * 16 + g;
        #pragma unroll
        for (int nt = 0; nt < 4; nt++) {
            int c = bn + wn * 32 + nt * 8 + t4 * 2;
            float b0 = bias[c], b1 = bias[c + 1];
            if (r < M)
                *(float2*)(C + (long)r * N + c) =
                    make_float2(acc[mt][nt][0] + b0, acc[mt][nt][1] + b1);
            if (r + 8 < M)
                *(float2*)(C + (long)(r + 8) * N + c) =
                    make_float2(acc[mt][nt][2] + b0, acc[mt][nt][3] + b1);
        }
    }
}

// ---------------- fused RMSNorm + RoPE (in-place, one row per CTA) ----------------
__global__ __launch_bounds__(384) void rmsnorm_rope_kernel(
    float* __restrict__ x, const float* __restrict__ gamma,
    const float* __restrict__ fc, const float* __restrict__ fs)
{
    __shared__ float red[12];
    __shared__ float rinv_s;
    const int row = blockIdx.x, tid = threadIdx.x;

    float4 v = *(float4*)(x + (long)row * DIM + tid * 4);
    float ss = v.x * v.x + v.y * v.y + v.z * v.z + v.w * v.w;
    #pragma unroll
    for (int s = 16; s > 0; s >>= 1) ss += __shfl_xor_sync(0xffffffffu, ss, s);
    if ((tid & 31) == 0) red[tid >> 5] = ss;
    __syncthreads();
    if (tid < 32) {
        float t = (tid < 12) ? red[tid] : 0.f;
        #pragma unroll
        for (int s = 16; s > 0; s >>= 1) t += __shfl_xor_sync(0xffffffffu, t, s);
        if (tid == 0) rinv_s = rsqrtf(t * (1.0f / DIM) + 1e-5f);
    }
    __syncthreads();
    float r = rinv_s;

    float4 g4 = *(const float4*)(gamma + tid * 4);
    float x0 = v.x * r * g4.x, x1 = v.y * r * g4.y;
    float x2 = v.z * r * g4.z, x3 = v.w * r * g4.w;

    int hd = (tid * 4) & (DH - 1);
    float4 c4 = *(const float4*)(fc + (long)row * DH + hd);
    float4 s4 = *(const float4*)(fs + (long)row * DH + hd);
    float4 o;
    o.x = x0 * c4.x - x1 * s4.y;
    o.y = x0 * s4.y + x1 * c4.x;
    o.z = x2 * c4.z - x3 * s4.w;
    o.w = x2 * s4.w + x3 * c4.z;
    *(float4*)(x + (long)row * DIM + tid * 4) = o;
}

// ---------------- fused block-sparse attention ----------------
// grid (13 qblocks, TQ, HEADS), 256 threads = 8 warps (4 M x 2 N)
// per CTA: 128 q rows x full DH; streams 64-key tiles from 1-2 selected blocks.
// softmax with fixed offset (scores bounded: q,k RMS-normalized) + exact zeroing
// of invalid tail columns.
#define ATT_QS 0
#define ATT_KS 16896                 // 128*132
#define ATT_VS (ATT_KS + 8448)       // + 64*132
#define ATT_PS (ATT_VS + 8704)       // + 64*136
#define ATT_RS (ATT_PS + 8704)       // + 128*68
#define ATT_SMEM_WORDS (ATT_RS + 256)

__global__ __launch_bounds__(256) void attention_kernel(
    const float* __restrict__ q, const float* __restrict__ k,
    const float* __restrict__ v, const int* __restrict__ sel,
    float* __restrict__ out)
{
    extern __shared__ unsigned sm[];
    unsigned* Qs = sm + ATT_QS;  // [128][132]
    unsigned* Ks = sm + ATT_KS;  // [64][132]
    unsigned* Vs = sm + ATT_VS;  // [64][136]
    unsigned* Ps = sm + ATT_PS;  // [128][68]
    float*    RS = (float*)(sm + ATT_RS);  // [128][2]

    const int qb = blockIdx.x, t = blockIdx.y, h = blockIdx.z;
    const int tid = threadIdx.x, warp = tid >> 5, lane = tid & 31;
    const int g = lane >> 2, t4 = lane & 3;
    const int wm = warp >> 1, wn = warp & 1;

    // load Q tile (convert to tf32, zero-fill tail rows)
    const float* qbase = q + (long)(t * HW) * DIM + (long)h * DH;
    {
        const int c4 = (tid & 31) * 4;
        const int lr0 = tid >> 5;
        #pragma unroll
        for (int i = 0; i < 16; i++) {
            int r = lr0 + i * 8;
            int qr = qb * 128 + r;
            float4 val = (qr < HW) ? *(const float4*)(qbase + (long)qr * DIM + c4)
                                   : make_float4(0.f, 0.f, 0.f, 0.f);
            *(uint4*)&Qs[r * 132 + c4] =
                make_uint4(f2tf(val.x), f2tf(val.y), f2tf(val.z), f2tf(val.w));
        }
    }

    float oacc[2][8][4] = {};
    float rpart[2][2] = {};

    int s0 = sel[t * 2 + 0]; if (s0 < 0) s0 = 0;
    int s1 = sel[t * 2 + 1];
    int nb = (s1 >= 0) ? 2 : 1;

    __syncthreads();

    const float SC   = 0.08838834764831843f * 1.4426950408889634f;  // (1/sqrt(DH))*log2(e)
    const float OFFL = 12.0f * 1.4426950408889634f;

    for (int bi = 0; bi < nb; bi++) {
        int blk = (bi == 0) ? s0 : s1;
        const float* kbp = k + (long)blk * HW * DIM + (long)h * DH;
        const float* vbp = v + (long)blk * HW * DIM + (long)h * DH;

        for (int n0 = 0; n0 < HW; n0 += 64) {
            // load K and V tiles
            {
                const int c4 = (tid & 31) * 4;
                const int lr0 = tid >> 5;
                #pragma unroll
                for (int i = 0; i < 8; i++) {
                    int r = lr0 + i * 8;
                    int kr = n0 + r;
                    float4 kv, vv;
                    if (kr < HW) {
                        kv = *(const float4*)(kbp + (long)kr * DIM + c4);
                        vv = *(const float4*)(vbp + (long)kr * DIM + c4);
                    } else {
                        kv = make_float4(0.f, 0.f, 0.f, 0.f);
                        vv = kv;
                    }
                    *(uint4*)&Ks[r * 132 + c4] =
                        make_uint4(f2tf(kv.x), f2tf(kv.y), f2tf(kv.z), f2tf(kv.w));
                    *(uint4*)&Vs[r * 136 + c4] =
                        make_uint4(f2tf(vv.x), f2tf(vv.y), f2tf(vv.z), f2tf(vv.w));
                }
            }
            __syncthreads();

            // QK^T : S[128][64], warp tile 32 rows x 32 keys
            float sacc[2][4][4] = {};
            #pragma unroll
            for (int ks = 0; ks < 16; ks++) {
                const int kb = ks * 8;
                unsigned a[2][4];
                #pragma unroll
                for (int mt = 0; mt < 2; mt++) {
                    int m = wm * 32 + mt * 16 + g;
                    a[mt][0] = Qs[m * 132 + kb + t4];
                    a[mt][1] = Qs[(m + 8) * 132 + kb + t4];
                    a[mt][2] = Qs[m * 132 + kb + t4 + 4];
                    a[mt][3] = Qs[(m + 8) * 132 + kb + t4 + 4];
                }
                #pragma unroll
                for (int nt = 0; nt < 4; nt++) {
                    int n = wn * 32 + nt * 8 + g;
                    unsigned b0 = Ks[n * 132 + kb + t4];
                    unsigned b1 = Ks[n * 132 + kb + t4 + 4];
                    mma_tf32(sacc[0][nt], a[0], b0, b1);
                    mma_tf32(sacc[1][nt], a[1], b0, b1);
                }
            }

            // exp (fixed offset), zero invalid columns exactly, stash P (tf32)
            #pragma unroll
            for (int mt = 0; mt < 2; mt++) {
                int rg = wm * 32 + mt * 16 + g;
                #pragma unroll
                for (int nt = 0; nt < 4; nt++) {
                    int cn = wn * 32 + nt * 8 + 2 * t4;
                    bool v0 = (n0 + cn) < HW, v1 = (n0 + cn + 1) < HW;
                    float p0 = v0 ? exp2f(fmaf(sacc[mt][nt][0], SC, -OFFL)) : 0.f;
                    float p1 = v1 ? exp2f(fmaf(sacc[mt][nt][1], SC, -OFFL)) : 0.f;
                    float p2 = v0 ? exp2f(fmaf(sacc[mt][nt][2], SC, -OFFL)) : 0.f;
                    float p3 = v1 ? exp2f(fmaf(sacc[mt][nt][3], SC, -OFFL)) : 0.f;
                    rpart[mt][0] += p0 + p1;
                    rpart[mt][1] += p2 + p3;
                    *(uint2*)&Ps[rg * 68 + cn]       = make_uint2(f2tf(p0), f2tf(p1));
                    *(uint2*)&Ps[(rg + 8) * 68 + cn] = make_uint2(f2tf(p2), f2tf(p3));
                }
            }
            __syncthreads();

            // P @ V : out += P[128][64] * V[64][128], warp tile 32 rows x 64 d
            #pragma unroll
            for (int ks = 0; ks < 8; ks++) {
                const int kb = ks * 8;
                unsigned a[2][4];
                #pragma unroll
                for (int mt = 0; mt < 2; mt++) {
                    int m = wm * 32 + mt * 16 + g;
                    a[mt][0] = Ps[m * 68 + kb + t4];
                    a[mt][1] = Ps[(m + 8) * 68 + kb + t4];
                    a[mt][2] = Ps[m * 68 + kb + t4 + 4];
                    a[mt][3] = Ps[(m + 8) * 68 + kb + t4 + 4];
                }
                #pragma unroll
                for (int nt = 0; nt < 8; nt++) {
                    int d = wn * 64 + nt * 8 + g;
                    unsigned b0 = Vs[(kb + t4) * 136 + d];
                    unsigned b1 = Vs[(kb + t4 + 4) * 136 + d];
                    mma_tf32(oacc[0][nt], a[0], b0, b1);
                    mma_tf32(oacc[1][nt], a[1], b0, b1);
                }
            }
            __syncthreads();
        }
    }

    // row-sum reduce: quad shuffle, then cross-warp via smem
    #pragma unroll
    for (int mt = 0; mt < 2; mt++) {
        #pragma unroll
        for (int hh = 0; hh < 2; hh++) {
            float s = rpart[mt][hh];
            s += __shfl_xor_sync(0xffffffffu, s, 1);
            s += __shfl_xor_sync(0xffffffffu, s, 2);
            if (t4 == 0) RS[(wm * 32 + mt * 16 + hh * 8 + g) * 2 + wn] = s;
        }
    }
    __syncthreads();

    float* obase = out + (long)(t * HW) * DIM + h * DH;
    #pragma unroll
    for (int mt = 0; mt < 2; mt++) {
        int r = wm * 32 + mt * 16 + g;
        float inv0 = 1.f / (RS[r * 2] + RS[r * 2 + 1]);
        float inv1 = 1.f / (RS[(r + 8) * 2] + RS[(r + 8) * 2 + 1]);
        int qr0 = qb * 128 + r, qr1 = qr0 + 8;
        #pragma unroll
        for (int nt = 0; nt < 8; nt++) {
            int d = wn * 64 + nt * 8 + 2 * t4;
            if (qr0 < HW)
                *(float2*)(obase + (long)qr0 * DIM + d) =
                    make_float2(oacc[mt][nt][0] * inv0, oacc[mt][nt][1] * inv0);
            if (qr1 < HW)
                *(float2*)(obase + (long)qr1 * DIM + d) =
                    make_float2(oacc[mt][nt][2] * inv1, oacc[mt][nt][3] * inv1);
        }
    }
}

// ---------------- launch ----------------
extern "C" void kernel_launch(void* const* d_in, const int* in_sizes, int n_in,
                              void* d_out, int out_size)
{
    const float* hidden  = (const float*)d_in[0];
    const float* history = (const float*)d_in[1];
    const float* fc   = (const float*)d_in[2];
    const float* fs   = (const float*)d_in[3];
    const float* fch  = (const float*)d_in[4];
    const float* fsh  = (const float*)d_in[5];
    const int*   sel  = (const int*)d_in[6];
    const float* Wq = (const float*)d_in[7];
    const float* bq = (const float*)d_in[8];
    const float* Wk = (const float*)d_in[9];
    const float* bk = (const float*)d_in[10];
    const float* Wv = (const float*)d_in[11];
    const float* bv = (const float*)d_in[12];
    const float* Wo = (const float*)d_in[13];
    const float* bo = (const float*)d_in[14];
    const float* gq = (const float*)d_in[15];
    const float* gk = (const float*)d_in[16];
    float* outp = (float*)d_out;

    float *qp, *kp, *vp, *ap;
    cudaGetSymbolAddress((void**)&qp, g_q);
    cudaGetSymbolAddress((void**)&kp, g_k);
    cudaGetSymbolAddress((void**)&vp, g_v);
    cudaGetSymbolAddress((void**)&ap, g_attn);

    cudaFuncSetAttribute(attention_kernel,
                         cudaFuncAttributeMaxDynamicSharedMemorySize,
                         ATT_SMEM_WORDS * 4);

    gemm_bias_tf32<<<dim3(12, 25), 256>>>(hidden,  Wq, bq, qp, QTOT, DIM, DIM);
    gemm_bias_tf32<<<dim3(12, 98), 256>>>(history, Wk, bk, kp, KTOT, DIM, DIM);
    gemm_bias_tf32<<<dim3(12, 98), 256>>>(history, Wv, bv, vp, KTOT, DIM, DIM);
    rmsnorm_rope_kernel<<<QTOT, 384>>>(qp, gq, fc, fs);
    rmsnorm_rope_kernel<<<KTOT, 384>>>(kp, gk, fch, fsh);
    attention_kernel<<<dim3(13, TQ, HEADS), 256, ATT_SMEM_WORDS * 4>>>(qp, kp, vp, sel, ap);
    gemm_bias_tf32<<<dim3(12, 25), 256>>>(ap, Wo, bo, outp, QTOT, DIM, DIM);
}

// round 2
// speedup vs baseline: 1.4171x; 1.4171x over previous
#include <cuda_runtime.h>

#define HW    1560
#define TQ    2
#define QTOT  3120
#define KTOT  12480
#define HEADS 12
#define DH    128
#define DIM   1536

// ---------------- scratch (device globals; no allocation allowed) ----------------
__device__ float g_q[QTOT * DIM];     // 19.2 MB
__device__ float g_k[KTOT * DIM];     // 76.7 MB
__device__ float g_v[KTOT * DIM];     // 76.7 MB
__device__ float g_attn[QTOT * DIM];  // 19.2 MB

// ---------------- helpers ----------------
__device__ __forceinline__ unsigned f2tf(float f) {
    unsigned u;
    asm("cvt.rna.tf32.f32 %0, %1;" : "=r"(u) : "f"(f));
    return u;
}

__device__ __forceinline__ void mma_tf32(float* d, const unsigned* a, unsigned b0, unsigned b1) {
    asm volatile(
        "mma.sync.aligned.m16n8k8.row.col.f32.tf32.tf32.f32 "
        "{%0,%1,%2,%3}, {%4,%5,%6,%7}, {%8,%9}, {%0,%1,%2,%3};"
        : "+f"(d[0]), "+f"(d[1]), "+f"(d[2]), "+f"(d[3])
        : "r"(a[0]), "r"(a[1]), "r"(a[2]), "r"(a[3]), "r"(b0), "r"(b1));
}

// true if k-block b is referenced by any (tq, kpq) selection (negatives never match)
__device__ __forceinline__ bool block_needed(int b, const int* __restrict__ sel) {
    return (sel[0] == b) | (sel[1] == b) | (sel[2] == b) | (sel[3] == b);
}

// ---------------- GEMM: C[M,N] = A[M,K] @ W[N,K]^T + bias[N]  (tf32 mma) ----------------
// block tile 128x128x32, 256 threads = 8 warps (2 M x 4 N), warp tile 64x32
// If sel != nullptr, CTAs whose 128-row slab overlaps no selected k-block exit early.
__global__ __launch_bounds__(256) void gemm_bias_tf32(
    const float* __restrict__ A, const float* __restrict__ W,
    const float* __restrict__ bias, float* __restrict__ C,
    int M, int N, int K, const int* __restrict__ sel)
{
    __shared__ unsigned As[128 * 36];  // [m][k], stride 36 -> bank = 4m+k, conflict-free
    __shared__ unsigned Ws[128 * 36];  // [n][k]

    const int bm = blockIdx.y * 128, bn = blockIdx.x * 128;

    if (sel) {
        int b0 = bm / HW;
        int b1 = (bm + 127) / HW;
        if (!block_needed(b0, sel) && !block_needed(b1, sel)) return;
    }

    const int tid  = threadIdx.x;
    const int warp = tid >> 5, lane = tid & 31;
    const int g = lane >> 2, t4 = lane & 3;
    const int wm = warp >> 2, wn = warp & 3;

    float acc[4][4][4] = {};

    const int lc = (tid & 7) * 4;  // col within 32-wide k tile (float4)
    const int lr = tid >> 3;       // base row (0..31), rows lr + 32*i

    float4 aF[4], wF[4];
    #pragma unroll
    for (int i = 0; i < 4; i++) {
        int row = lr + 32 * i;
        long ar = bm + row;
        aF[i] = (ar < M) ? *(const float4*)(A + ar * (long)K + lc)
                         : make_float4(0.f, 0.f, 0.f, 0.f);
        wF[i] = *(const float4*)(W + (long)(bn + row) * K + lc);
    }

    const int KT = K >> 5;
    for (int kt = 0; kt < KT; kt++) {
        #pragma unroll
        for (int i = 0; i < 4; i++) {
            int row = lr + 32 * i;
            *(uint4*)&As[row * 36 + lc] =
                make_uint4(f2tf(aF[i].x), f2tf(aF[i].y), f2tf(aF[i].z), f2tf(aF[i].w));
            *(uint4*)&Ws[row * 36 + lc] =
                make_uint4(f2tf(wF[i].x), f2tf(wF[i].y), f2tf(wF[i].z), f2tf(wF[i].w));
        }
        __syncthreads();

        if (kt + 1 < KT) {
            int k0 = (kt + 1) << 5;
            #pragma unroll
            for (int i = 0; i < 4; i++) {
                int row = lr + 32 * i;
                long ar = bm + row;
                aF[i] = (ar < M) ? *(const float4*)(A + ar * (long)K + k0 + lc)
                                 : make_float4(0.f, 0.f, 0.f, 0.f);
                wF[i] = *(const float4*)(W + (long)(bn + row) * K + k0 + lc);
            }
        }

        #pragma unroll
        for (int kk = 0; kk < 4; kk++) {
            const int kb = kk * 8;
            unsigned a[4][4];
            #pragma unroll
            for (int mt = 0; mt < 4; mt++) {
                int m = wm * 64 + mt * 16 + g;
                a[mt][0] = As[m * 36 + kb + t4];
                a[mt][1] = As[(m + 8) * 36 + kb + t4];
                a[mt][2] = As[m * 36 + kb + t4 + 4];
                a[mt][3] = As[(m + 8) * 36 + kb + t4 + 4];
            }
            #pragma unroll
            for (int nt = 0; nt < 4; nt++) {
                int n = wn * 32 + nt * 8 + g;
                unsigned b0 = Ws[n * 36 + kb + t4];
                unsigned b1 = Ws[n * 36 + kb + t4 + 4];
                #pragma unroll
                for (int mt = 0; mt < 4; mt++) mma_tf32(acc[mt][nt], a[mt], b0, b1);
            }
        }
        __syncthreads();
    }

    #pragma unroll
    for (int mt = 0; mt < 4; mt++) {
        int r = bm + wm * 64 + mt * 16 + g;
        #pragma unroll
        for (int nt = 0; nt < 4; nt++) {
            int c = bn + wn * 32 + nt * 8 + t4 * 2;
            float b0 = bias[c], b1 = bias[c + 1];
            if (r < M)
                *(float2*)(C + (long)r * N + c) =
                    make_float2(acc[mt][nt][0] + b0, acc[mt][nt][1] + b1);
            if (r + 8 < M)
                *(float2*)(C + (long)(r + 8) * N + c) =
                    make_float2(acc[mt][nt][2] + b0, acc[mt][nt][3] + b1);
        }
    }
}

// ---------------- fused RMSNorm + RoPE (in-place, one row per CTA) ----------------
__global__ __launch_bounds__(384) void rmsnorm_rope_kernel(
    float* __restrict__ x, const float* __restrict__ gamma,
    const float* __restrict__ fc, const float* __restrict__ fs,
    const int* __restrict__ sel)
{
    __shared__ float red[12];
    __shared__ float rinv_s;
    const int row = blockIdx.x, tid = threadIdx.x;

    if (sel && !block_needed(row / HW, sel)) return;

    float4 v = *(float4*)(x + (long)row * DIM + tid * 4);
    float ss = v.x * v.x + v.y * v.y + v.z * v.z + v.w * v.w;
    #pragma unroll
    for (int s = 16; s > 0; s >>= 1) ss += __shfl_xor_sync(0xffffffffu, ss, s);
    if ((tid & 31) == 0) red[tid >> 5] = ss;
    __syncthreads();
    if (tid < 32) {
        float t = (tid < 12) ? red[tid] : 0.f;
        #pragma unroll
        for (int s = 16; s > 0; s >>= 1) t += __shfl_xor_sync(0xffffffffu, t, s);
        if (tid == 0) rinv_s = rsqrtf(t * (1.0f / DIM) + 1e-5f);
    }
    __syncthreads();
    float r = rinv_s;

    float4 g4 = *(const float4*)(gamma + tid * 4);
    float x0 = v.x * r * g4.x, x1 = v.y * r * g4.y;
    float x2 = v.z * r * g4.z, x3 = v.w * r * g4.w;

    int hd = (tid * 4) & (DH - 1);
    float4 c4 = *(const float4*)(fc + (long)row * DH + hd);
    float4 s4 = *(const float4*)(fs + (long)row * DH + hd);
    float4 o;
    o.x = x0 * c4.x - x1 * s4.y;
    o.y = x0 * s4.y + x1 * c4.x;
    o.z = x2 * c4.z - x3 * s4.w;
    o.w = x2 * s4.w + x3 * c4.z;
    *(float4*)(x + (long)row * DIM + tid * 4) = o;
}

// ---------------- fused block-sparse attention ----------------
// grid (13 qblocks, TQ, HEADS), 256 threads = 8 warps (4 M x 2 N)
// per CTA: 128 q rows x full DH; streams 64-key tiles from 1-2 selected blocks.
// softmax with fixed offset (scores bounded: q,k RMS-normalized) + exact zeroing
// of invalid tail columns.
#define ATT_QS 0
#define ATT_KS 16896                 // 128*132
#define ATT_VS (ATT_KS + 8448)       // + 64*132
#define ATT_PS (ATT_VS + 8704)       // + 64*136
#define ATT_RS (ATT_PS + 8704)       // + 128*68
#define ATT_SMEM_WORDS (ATT_RS + 256)

__global__ __launch_bounds__(256) void attention_kernel(
    const float* __restrict__ q, const float* __restrict__ k,
    const float* __restrict__ v, const int* __restrict__ sel,
    float* __restrict__ out)
{
    extern __shared__ unsigned sm[];
    unsigned* Qs = sm + ATT_QS;  // [128][132]
    unsigned* Ks = sm + ATT_KS;  // [64][132]
    unsigned* Vs = sm + ATT_VS;  // [64][136]
    unsigned* Ps = sm + ATT_PS;  // [128][68]
    float*    RS = (float*)(sm + ATT_RS);  // [128][2]

    const int qb = blockIdx.x, t = blockIdx.y, h = blockIdx.z;
    const int tid = threadIdx.x, warp = tid >> 5, lane = tid & 31;
    const int g = lane >> 2, t4 = lane & 3;
    const int wm = warp >> 1, wn = warp & 1;

    // load Q tile (convert to tf32, zero-fill tail rows)
    const float* qbase = q + (long)(t * HW) * DIM + (long)h * DH;
    {
        const int c4 = (tid & 31) * 4;
        const int lr0 = tid >> 5;
        #pragma unroll
        for (int i = 0; i < 16; i++) {
            int r = lr0 + i * 8;
            int qr = qb * 128 + r;
            float4 val = (qr < HW) ? *(const float4*)(qbase + (long)qr * DIM + c4)
                                   : make_float4(0.f, 0.f, 0.f, 0.f);
            *(uint4*)&Qs[r * 132 + c4] =
                make_uint4(f2tf(val.x), f2tf(val.y), f2tf(val.z), f2tf(val.w));
        }
    }

    float oacc[2][8][4] = {};
    float rpart[2][2] = {};

    int s0 = sel[t * 2 + 0]; if (s0 < 0) s0 = 0;
    int s1 = sel[t * 2 + 1];
    int nb = (s1 >= 0) ? 2 : 1;

    __syncthreads();

    const float SC   = 0.08838834764831843f * 1.4426950408889634f;  // (1/sqrt(DH))*log2(e)
    const float OFFL = 12.0f * 1.4426950408889634f;

    for (int bi = 0; bi < nb; bi++) {
        int blk = (bi == 0) ? s0 : s1;
        const float* kbp = k + (long)blk * HW * DIM + (long)h * DH;
        const float* vbp = v + (long)blk * HW * DIM + (long)h * DH;

        for (int n0 = 0; n0 < HW; n0 += 64) {
            // load K and V tiles
            {
                const int c4 = (tid & 31) * 4;
                const int lr0 = tid >> 5;
                #pragma unroll
                for (int i = 0; i < 8; i++) {
                    int r = lr0 + i * 8;
                    int kr = n0 + r;
                    float4 kv, vv;
                    if (kr < HW) {
                        kv = *(const float4*)(kbp + (long)kr * DIM + c4);
                        vv = *(const float4*)(vbp + (long)kr * DIM + c4);
                    } else {
                        kv = make_float4(0.f, 0.f, 0.f, 0.f);
                        vv = kv;
                    }
                    *(uint4*)&Ks[r * 132 + c4] =
                        make_uint4(f2tf(kv.x), f2tf(kv.y), f2tf(kv.z), f2tf(kv.w));
                    *(uint4*)&Vs[r * 136 + c4] =
                        make_uint4(f2tf(vv.x), f2tf(vv.y), f2tf(vv.z), f2tf(vv.w));
                }
            }
            __syncthreads();

            // QK^T : S[128][64], warp tile 32 rows x 32 keys
            float sacc[2][4][4] = {};
            #pragma unroll
            for (int ks = 0; ks < 16; ks++) {
                const int kb = ks * 8;
                unsigned a[2][4];
                #pragma unroll
                for (int mt = 0; mt < 2; mt++) {
                    int m = wm * 32 + mt * 16 + g;
                    a[mt][0] = Qs[m * 132 + kb + t4];
                    a[mt][1] = Qs[(m + 8) * 132 + kb + t4];
                    a[mt][2] = Qs[m * 132 + kb + t4 + 4];
                    a[mt][3] = Qs[(m + 8) * 132 + kb + t4 + 4];
                }
                #pragma unroll
                for (int nt = 0; nt < 4; nt++) {
                    int n = wn * 32 + nt * 8 + g;
                    unsigned b0 = Ks[n * 132 + kb + t4];
                    unsigned b1 = Ks[n * 132 + kb + t4 + 4];
                    mma_tf32(sacc[0][nt], a[0], b0, b1);
                    mma_tf32(sacc[1][nt], a[1], b0, b1);
                }
            }

            // exp (fixed offset), zero invalid columns exactly, stash P (tf32)
            #pragma unroll
            for (int mt = 0; mt < 2; mt++) {
                int rg = wm * 32 + mt * 16 + g;
                #pragma unroll
                for (int nt = 0; nt < 4; nt++) {
                    int cn = wn * 32 + nt * 8 + 2 * t4;
                    bool v0 = (n0 + cn) < HW, v1 = (n0 + cn + 1) < HW;
                    float p0 = v0 ? exp2f(fmaf(sacc[mt][nt][0], SC, -OFFL)) : 0.f;
                    float p1 = v1 ? exp2f(fmaf(sacc[mt][nt][1], SC, -OFFL)) : 0.f;
                    float p2 = v0 ? exp2f(fmaf(sacc[mt][nt][2], SC, -OFFL)) : 0.f;
                    float p3 = v1 ? exp2f(fmaf(sacc[mt][nt][3], SC, -OFFL)) : 0.f;
                    rpart[mt][0] += p0 + p1;
                    rpart[mt][1] += p2 + p3;
                    *(uint2*)&Ps[rg * 68 + cn]       = make_uint2(f2tf(p0), f2tf(p1));
                    *(uint2*)&Ps[(rg + 8) * 68 + cn] = make_uint2(f2tf(p2), f2tf(p3));
                }
            }
            __syncthreads();

            // P @ V : out += P[128][64] * V[64][128], warp tile 32 rows x 64 d
            #pragma unroll
            for (int ks = 0; ks < 8; ks++) {
                const int kb = ks * 8;
                unsigned a[2][4];
                #pragma unroll
                for (int mt = 0; mt < 2; mt++) {
                    int m = wm * 32 + mt * 16 + g;
                    a[mt][0] = Ps[m * 68 + kb + t4];
                    a[mt][1] = Ps[(m + 8) * 68 + kb + t4];
                    a[mt][2] = Ps[m * 68 + kb + t4 + 4];
                    a[mt][3] = Ps[(m + 8) * 68 + kb + t4 + 4];
                }
                #pragma unroll
                for (int nt = 0; nt < 8; nt++) {
                    int d = wn * 64 + nt * 8 + g;
                    unsigned b0 = Vs[(kb + t4) * 136 + d];
                    unsigned b1 = Vs[(kb + t4 + 4) * 136 + d];
                    mma_tf32(oacc[0][nt], a[0], b0, b1);
                    mma_tf32(oacc[1][nt], a[1], b0, b1);
                }
            }
            __syncthreads();
        }
    }

    // row-sum reduce: quad shuffle, then cross-warp via smem
    #pragma unroll
    for (int mt = 0; mt < 2; mt++) {
        #pragma unroll
        for (int hh = 0; hh < 2; hh++) {
            float s = rpart[mt][hh];
            s += __shfl_xor_sync(0xffffffffu, s, 1);
            s += __shfl_xor_sync(0xffffffffu, s, 2);
            if (t4 == 0) RS[(wm * 32 + mt * 16 + hh * 8 + g) * 2 + wn] = s;
        }
    }
    __syncthreads();

    float* obase = out + (long)(t * HW) * DIM + h * DH;
    #pragma unroll
    for (int mt = 0; mt < 2; mt++) {
        int r = wm * 32 + mt * 16 + g;
        float inv0 = 1.f / (RS[r * 2] + RS[r * 2 + 1]);
        float inv1 = 1.f / (RS[(r + 8) * 2] + RS[(r + 8) * 2 + 1]);
        int qr0 = qb * 128 + r, qr1 = qr0 + 8;
        #pragma unroll
        for (int nt = 0; nt < 8; nt++) {
            int d = wn * 64 + nt * 8 + 2 * t4;
            if (qr0 < HW)
                *(float2*)(obase + (long)qr0 * DIM + d) =
                    make_float2(oacc[mt][nt][0] * inv0, oacc[mt][nt][1] * inv0);
            if (qr1 < HW)
                *(float2*)(obase + (long)qr1 * DIM + d) =
                    make_float2(oacc[mt][nt][2] * inv1, oacc[mt][nt][3] * inv1);
        }
    }
}

// ---------------- launch ----------------
extern "C" void kernel_launch(void* const* d_in, const int* in_sizes, int n_in,
                              void* d_out, int out_size)
{
    const float* hidden  = (const float*)d_in[0];
    const float* history = (const float*)d_in[1];
    const float* fc   = (const float*)d_in[2];
    const float* fs   = (const float*)d_in[3];
    const float* fch  = (const float*)d_in[4];
    const float* fsh  = (const float*)d_in[5];
    const int*   sel  = (const int*)d_in[6];
    const float* Wq = (const float*)d_in[7];
    const float* bq = (const float*)d_in[8];
    const float* Wk = (const float*)d_in[9];
    const float* bk = (const float*)d_in[10];
    const float* Wv = (const float*)d_in[11];
    const float* bv = (const float*)d_in[12];
    const float* Wo = (const float*)d_in[13];
    const float* bo = (const float*)d_in[14];
    const float* gq = (const float*)d_in[15];
    const float* gk = (const float*)d_in[16];
    float* outp = (float*)d_out;

    float *qp, *kp, *vp, *ap;
    cudaGetSymbolAddress((void**)&qp, g_q);
    cudaGetSymbolAddress((void**)&kp, g_k);
    cudaGetSymbolAddress((void**)&vp, g_v);
    cudaGetSymbolAddress((void**)&ap, g_attn);

    cudaFuncSetAttribute(attention_kernel,
                         cudaFuncAttributeMaxDynamicSharedMemorySize,
                         ATT_SMEM_WORDS * 4);

    gemm_bias_tf32<<<dim3(12, 25), 256>>>(hidden,  Wq, bq, qp, QTOT, DIM, DIM, nullptr);
    gemm_bias_tf32<<<dim3(12, 98), 256>>>(history, Wk, bk, kp, KTOT, DIM, DIM, sel);
    gemm_bias_tf32<<<dim3(12, 98), 256>>>(history, Wv, bv, vp, KTOT, DIM, DIM, sel);
    rmsnorm_rope_kernel<<<QTOT, 384>>>(qp, gq, fc, fs, nullptr);
    rmsnorm_rope_kernel<<<KTOT, 384>>>(kp, gk, fch, fsh, sel);
    attention_kernel<<<dim3(13, TQ, HEADS), 256, ATT_SMEM_WORDS * 4>>>(qp, kp, vp, sel, ap);
    gemm_bias_tf32<<<dim3(12, 25), 256>>>(ap, Wo, bo, outp, QTOT, DIM, DIM, nullptr);
}

// round 4
// speedup vs baseline: 1.5095x; 1.0652x over previous
#include <cuda_runtime.h>

#define HW    1560
#define TQ    2
#define QTOT  3120
#define KTOT  12480
#define HEADS 12
#define DH    128
#define DIM   1536

// ---------------- scratch (device globals; no allocation allowed) ----------------
__device__ float g_q[QTOT * DIM];
__device__ float g_k[KTOT * DIM];
__device__ float g_v[KTOT * DIM];
__device__ float g_attn[QTOT * DIM];

// ---------------- helpers ----------------
__device__ __forceinline__ unsigned f2tf(float f) {
    unsigned u;
    asm("cvt.rna.tf32.f32 %0, %1;" : "=r"(u) : "f"(f));
    return u;
}

__device__ __forceinline__ void mma_tf32(float* d, const unsigned* a, unsigned b0, unsigned b1) {
    asm volatile(
        "mma.sync.aligned.m16n8k8.row.col.f32.tf32.tf32.f32 "
        "{%0,%1,%2,%3}, {%4,%5,%6,%7}, {%8,%9}, {%0,%1,%2,%3};"
        : "+f"(d[0]), "+f"(d[1]), "+f"(d[2]), "+f"(d[3])
        : "r"(a[0]), "r"(a[1]), "r"(a[2]), "r"(a[3]), "r"(b0), "r"(b1));
}

__device__ __forceinline__ bool block_needed(int b, const int* __restrict__ sel) {
    return (sel[0] == b) | (sel[1] == b) | (sel[2] == b) | (sel[3] == b);
}

// ---------------- GEMM: C[M,N] = A[M,K] @ W[N,K]^T + bias[N]  (tf32 mma) ----------------
// block tile 128x128x32, 256 threads = 8 warps (2 M x 4 N), warp tile 64x32
// Ping-pong double-buffered smem: ONE __syncthreads per k-tile; STS(k+1) into the
// other stage overlaps MMA(k); LDG(k+1) issued before compute.
#define GEMM_STAGE (128 * 36)
#define GEMM_SMEM  (2 * 2 * GEMM_STAGE * 4)   // 2 stages x (As+Ws) x 4B = 73728

__global__ __launch_bounds__(256, 1) void gemm_bias_tf32(
    const float* __restrict__ A, const float* __restrict__ W,
    const float* __restrict__ bias, float* __restrict__ C,
    int M, int N, int K, const int* __restrict__ sel)
{
    extern __shared__ unsigned gsm[];
    // stage s: As = gsm + s*2*GEMM_STAGE, Ws = As + GEMM_STAGE
    const int bm = blockIdx.y * 128, bn = blockIdx.x * 128;

    if (sel) {
        int b0 = bm / HW;
        int b1 = (bm + 127) / HW;
        if (!block_needed(b0, sel) && !block_needed(b1, sel)) return;
    }

    const int tid  = threadIdx.x;
    const int warp = tid >> 5, lane = tid & 31;
    const int g = lane >> 2, t4 = lane & 3;
    const int wm = warp >> 2, wn = warp & 3;

    float acc[4][4][4] = {};

    const int lc = (tid & 7) * 4;  // col within 32-wide k tile (float4)
    const int lr = tid >> 3;       // base row (0..31), rows lr + 32*i

    float4 aF[4], wF[4];
    #pragma unroll
    for (int i = 0; i < 4; i++) {
        int row = lr + 32 * i;
        long ar = bm + row;
        aF[i] = (ar < M) ? *(const float4*)(A + ar * (long)K + lc)
                         : make_float4(0.f, 0.f, 0.f, 0.f);
        wF[i] = *(const float4*)(W + (long)(bn + row) * K + lc);
    }

    // prime stage 0
    {
        unsigned* As = gsm;
        unsigned* Ws = gsm + GEMM_STAGE;
        #pragma unroll
        for (int i = 0; i < 4; i++) {
            int row = lr + 32 * i;
            *(uint4*)&As[row * 36 + lc] =
                make_uint4(f2tf(aF[i].x), f2tf(aF[i].y), f2tf(aF[i].z), f2tf(aF[i].w));
            *(uint4*)&Ws[row * 36 + lc] =
                make_uint4(f2tf(wF[i].x), f2tf(wF[i].y), f2tf(wF[i].z), f2tf(wF[i].w));
        }
    }
    __syncthreads();

    const int KT = K >> 5;
    for (int kt = 0; kt < KT; kt++) {
        const unsigned* As = gsm + (kt & 1) * 2 * GEMM_STAGE;
        const unsigned* Ws = As + GEMM_STAGE;

        // issue global loads for next tile (latency hidden under compute)
        if (kt + 1 < KT) {
            int k0 = (kt + 1) << 5;
            #pragma unroll
            for (int i = 0; i < 4; i++) {
                int row = lr + 32 * i;
                long ar = bm + row;
                aF[i] = (ar < M) ? *(const float4*)(A + ar * (long)K + k0 + lc)
                                 : make_float4(0.f, 0.f, 0.f, 0.f);
                wF[i] = *(const float4*)(W + (long)(bn + row) * K + k0 + lc);
            }
        }

        #pragma unroll
        for (int kk = 0; kk < 4; kk++) {
            const int kb = kk * 8;
            unsigned a[4][4];
            #pragma unroll
            for (int mt = 0; mt < 4; mt++) {
                int m = wm * 64 + mt * 16 + g;
                a[mt][0] = As[m * 36 + kb + t4];
                a[mt][1] = As[(m + 8) * 36 + kb + t4];
                a[mt][2] = As[m * 36 + kb + t4 + 4];
                a[mt][3] = As[(m + 8) * 36 + kb + t4 + 4];
            }
            #pragma unroll
            for (int nt = 0; nt < 4; nt++) {
                int n = wn * 32 + nt * 8 + g;
                unsigned b0 = Ws[n * 36 + kb + t4];
                unsigned b1 = Ws[n * 36 + kb + t4 + 4];
                #pragma unroll
                for (int mt = 0; mt < 4; mt++) mma_tf32(acc[mt][nt], a[mt], b0, b1);
            }
        }

        // store next tile into the other stage (no hazard with current compute)
        if (kt + 1 < KT) {
            unsigned* Asn = gsm + ((kt + 1) & 1) * 2 * GEMM_STAGE;
            unsigned* Wsn = Asn + GEMM_STAGE;
            #pragma unroll
            for (int i = 0; i < 4; i++) {
                int row = lr + 32 * i;
                *(uint4*)&Asn[row * 36 + lc] =
                    make_uint4(f2tf(aF[i].x), f2tf(aF[i].y), f2tf(aF[i].z), f2tf(aF[i].w));
                *(uint4*)&Wsn[row * 36 + lc] =
                    make_uint4(f2tf(wF[i].x), f2tf(wF[i].y), f2tf(wF[i].z), f2tf(wF[i].w));
            }
        }
        __syncthreads();
    }

    #pragma unroll
    for (int mt = 0; mt < 4; mt++) {
        int r = bm + wm * 64 + mt * 16 + g;
        #pragma unroll
        for (int nt = 0; nt < 4; nt++) {
            int c = bn + wn * 32 + nt * 8 + t4 * 2;
            float b0 = bias[c], b1 = bias[c + 1];
            if (r < M)
                *(float2*)(C + (long)r * N + c) =
                    make_float2(acc[mt][nt][0] + b0, acc[mt][nt][1] + b1);
            if (r + 8 < M)
                *(float2*)(C + (long)(r + 8) * N + c) =
                    make_float2(acc[mt][nt][2] + b0, acc[mt][nt][3] + b1);
        }
    }
}

// ---------------- fused RMSNorm + RoPE (in-place, one row per CTA) ----------------
__global__ __launch_bounds__(384) void rmsnorm_rope_kernel(
    float* __restrict__ x, const float* __restrict__ gamma,
    const float* __restrict__ fc, const float* __restrict__ fs,
    const int* __restrict__ sel)
{
    __shared__ float red[12];
    __shared__ float rinv_s;
    const int row = blockIdx.x, tid = threadIdx.x;

    if (sel && !block_needed(row / HW, sel)) return;

    float4 v = *(float4*)(x + (long)row * DIM + tid * 4);
    float ss = v.x * v.x + v.y * v.y + v.z * v.z + v.w * v.w;
    #pragma unroll
    for (int s = 16; s > 0; s >>= 1) ss += __shfl_xor_sync(0xffffffffu, ss, s);
    if ((tid & 31) == 0) red[tid >> 5] = ss;
    __syncthreads();
    if (tid < 32) {
        float t = (tid < 12) ? red[tid] : 0.f;
        #pragma unroll
        for (int s = 16; s > 0; s >>= 1) t += __shfl_xor_sync(0xffffffffu, t, s);
        if (tid == 0) rinv_s = rsqrtf(t * (1.0f / DIM) + 1e-5f);
    }
    __syncthreads();
    float r = rinv_s;

    float4 g4 = *(const float4*)(gamma + tid * 4);
    float x0 = v.x * r * g4.x, x1 = v.y * r * g4.y;
    float x2 = v.z * r * g4.z, x3 = v.w * r * g4.w;

    int hd = (tid * 4) & (DH - 1);
    float4 c4 = *(const float4*)(fc + (long)row * DH + hd);
    float4 s4 = *(const float4*)(fs + (long)row * DH + hd);
    float4 o;
    o.x = x0 * c4.x - x1 * s4.y;
    o.y = x0 * s4.y + x1 * c4.x;
    o.z = x2 * c4.z - x3 * s4.w;
    o.w = x2 * s4.w + x3 * c4.z;
    *(float4*)(x + (long)row * DIM + tid * 4) = o;
}

// ---------------- fused block-sparse attention ----------------
// grid (13 qblocks, TQ, HEADS), 256 threads = 8 warps (4 M x 2 N)
// Middle sync (softmax->PV) is pairwise: only the 2 warps sharing a wm row-group
// exchange P columns -> named barrier (wm+1, 64 threads).
#define ATT_QS 0
#define ATT_KS 16896                 // 128*132
#define ATT_VS (ATT_KS + 8448)       // + 64*132
#define ATT_PS (ATT_VS + 8704)       // + 64*136
#define ATT_RS (ATT_PS + 8704)       // + 128*68
#define ATT_SMEM_WORDS (ATT_RS + 256)

__global__ __launch_bounds__(256) void attention_kernel(
    const float* __restrict__ q, const float* __restrict__ k,
    const float* __restrict__ v, const int* __restrict__ sel,
    float* __restrict__ out)
{
    extern __shared__ unsigned sm[];
    unsigned* Qs = sm + ATT_QS;
    unsigned* Ks = sm + ATT_KS;
    unsigned* Vs = sm + ATT_VS;
    unsigned* Ps = sm + ATT_PS;
    float*    RS = (float*)(sm + ATT_RS);

    const int qb = blockIdx.x, t = blockIdx.y, h = blockIdx.z;
    const int tid = threadIdx.x, warp = tid >> 5, lane = tid & 31;
    const int g = lane >> 2, t4 = lane & 3;
    const int wm = warp >> 1, wn = warp & 1;

    const float* qbase = q + (long)(t * HW) * DIM + (long)h * DH;
    {
        const int c4 = (tid & 31) * 4;
        const int lr0 = tid >> 5;
        #pragma unroll
        for (int i = 0; i < 16; i++) {
            int r = lr0 + i * 8;
            int qr = qb * 128 + r;
            float4 val = (qr < HW) ? *(const float4*)(qbase + (long)qr * DIM + c4)
                                   : make_float4(0.f, 0.f, 0.f, 0.f);
            *(uint4*)&Qs[r * 132 + c4] =
                make_uint4(f2tf(val.x), f2tf(val.y), f2tf(val.z), f2tf(val.w));
        }
    }

    float oacc[2][8][4] = {};
    float rpart[2][2] = {};

    int s0 = sel[t * 2 + 0]; if (s0 < 0) s0 = 0;
    int s1 = sel[t * 2 + 1];
    int nb = (s1 >= 0) ? 2 : 1;

    __syncthreads();

    const float SC   = 0.08838834764831843f * 1.4426950408889634f;
    const float OFFL = 12.0f * 1.4426950408889634f;

    for (int bi = 0; bi < nb; bi++) {
        int blk = (bi == 0) ? s0 : s1;
        const float* kbp = k + (long)blk * HW * DIM + (long)h * DH;
        const float* vbp = v + (long)blk * HW * DIM + (long)h * DH;

        for (int n0 = 0; n0 < HW; n0 += 64) {
            {
                const int c4 = (tid & 31) * 4;
                const int lr0 = tid >> 5;
                #pragma unroll
                for (int i = 0; i < 8; i++) {
                    int r = lr0 + i * 8;
                    int kr = n0 + r;
                    float4 kv, vv;
                    if (kr < HW) {
                        kv = *(const float4*)(kbp + (long)kr * DIM + c4);
                        vv = *(const float4*)(vbp + (long)kr * DIM + c4);
                    } else {
                        kv = make_float4(0.f, 0.f, 0.f, 0.f);
                        vv = kv;
                    }
                    *(uint4*)&Ks[r * 132 + c4] =
                        make_uint4(f2tf(kv.x), f2tf(kv.y), f2tf(kv.z), f2tf(kv.w));
                    *(uint4*)&Vs[r * 136 + c4] =
                        make_uint4(f2tf(vv.x), f2tf(vv.y), f2tf(vv.z), f2tf(vv.w));
                }
            }
            __syncthreads();

            float sacc[2][4][4] = {};
            #pragma unroll
            for (int ks = 0; ks < 16; ks++) {
                const int kb = ks * 8;
                unsigned a[2][4];
                #pragma unroll
                for (int mt = 0; mt < 2; mt++) {
                    int m = wm * 32 + mt * 16 + g;
                    a[mt][0] = Qs[m * 132 + kb + t4];
                    a[mt][1] = Qs[(m + 8) * 132 + kb + t4];
                    a[mt][2] = Qs[m * 132 + kb + t4 + 4];
                    a[mt][3] = Qs[(m + 8) * 132 + kb + t4 + 4];
                }
                #pragma unroll
                for (int nt = 0; nt < 4; nt++) {
                    int n = wn * 32 + nt * 8 + g;
                    unsigned b0 = Ks[n * 132 + kb + t4];
                    unsigned b1 = Ks[n * 132 + kb + t4 + 4];
                    mma_tf32(sacc[0][nt], a[0], b0, b1);
                    mma_tf32(sacc[1][nt], a[1], b0, b1);
                }
            }

            #pragma unroll
            for (int mt = 0; mt < 2; mt++) {
                int rg = wm * 32 + mt * 16 + g;
                #pragma unroll
                for (int nt = 0; nt < 4; nt++) {
                    int cn = wn * 32 + nt * 8 + 2 * t4;
                    bool v0 = (n0 + cn) < HW, v1 = (n0 + cn + 1) < HW;
                    float p0 = v0 ? exp2f(fmaf(sacc[mt][nt][0], SC, -OFFL)) : 0.f;
                    float p1 = v1 ? exp2f(fmaf(sacc[mt][nt][1], SC, -OFFL)) : 0.f;
                    float p2 = v0 ? exp2f(fmaf(sacc[mt][nt][2], SC, -OFFL)) : 0.f;
                    float p3 = v1 ? exp2f(fmaf(sacc[mt][nt][3], SC, -OFFL)) : 0.f;
                    rpart[mt][0] += p0 + p1;
                    rpart[mt][1] += p2 + p3;
                    *(uint2*)&Ps[rg * 68 + cn]       = make_uint2(f2tf(p0), f2tf(p1));
                    *(uint2*)&Ps[(rg + 8) * 68 + cn] = make_uint2(f2tf(p2), f2tf(p3));
                }
            }
            // only the 2 warps sharing this wm row-group exchange P columns
            asm volatile("bar.sync %0, %1;" :: "r"(wm + 1), "r"(64) : "memory");

            #pragma unroll
            for (int ks = 0; ks < 8; ks++) {
                const int kb = ks * 8;
                unsigned a[2][4];
                #pragma unroll
                for (int mt = 0; mt < 2; mt++) {
                    int m = wm * 32 + mt * 16 + g;
                    a[mt][0] = Ps[m * 68 + kb + t4];
                    a[mt][1] = Ps[(m + 8) * 68 + kb + t4];
                    a[mt][2] = Ps[m * 68 + kb + t4 + 4];
                    a[mt][3] = Ps[(m + 8) * 68 + kb + t4 + 4];
                }
                #pragma unroll
                for (int nt = 0; nt < 8; nt++) {
                    int d = wn * 64 + nt * 8 + g;
                    unsigned b0 = Vs[(kb + t4) * 136 + d];
                    unsigned b1 = Vs[(kb + t4 + 4) * 136 + d];
                    mma_tf32(oacc[0][nt], a[0], b0, b1);
                    mma_tf32(oacc[1][nt], a[1], b0, b1);
                }
            }
            __syncthreads();
        }
    }

    #pragma unroll
    for (int mt = 0; mt < 2; mt++) {
        #pragma unroll
        for (int hh = 0; hh < 2; hh++) {
            float s = rpart[mt][hh];
            s += __shfl_xor_sync(0xffffffffu, s, 1);
            s += __shfl_xor_sync(0xffffffffu, s, 2);
            if (t4 == 0) RS[(wm * 32 + mt * 16 + hh * 8 + g) * 2 + wn] = s;
        }
    }
    __syncthreads();

    float* obase = out + (long)(t * HW) * DIM + h * DH;
    #pragma unroll
    for (int mt = 0; mt < 2; mt++) {
        int r = wm * 32 + mt * 16 + g;
        float inv0 = 1.f / (RS[r * 2] + RS[r * 2 + 1]);
        float inv1 = 1.f / (RS[(r + 8) * 2] + RS[(r + 8) * 2 + 1]);
        int qr0 = qb * 128 + r, qr1 = qr0 + 8;
        #pragma unroll
        for (int nt = 0; nt < 8; nt++) {
            int d = wn * 64 + nt * 8 + 2 * t4;
            if (qr0 < HW)
                *(float2*)(obase + (long)qr0 * DIM + d) =
                    make_float2(oacc[mt][nt][0] * inv0, oacc[mt][nt][1] * inv0);
            if (qr1 < HW)
                *(float2*)(obase + (long)qr1 * DIM + d) =
                    make_float2(oacc[mt][nt][2] * inv1, oacc[mt][nt][3] * inv1);
        }
    }
}

// ---------------- launch ----------------
extern "C" void kernel_launch(void* const* d_in, const int* in_sizes, int n_in,
                              void* d_out, int out_size)
{
    const float* hidden  = (const float*)d_in[0];
    const float* history = (const float*)d_in[1];
    const float* fc   = (const float*)d_in[2];
    const float* fs   = (const float*)d_in[3];
    const float* fch  = (const float*)d_in[4];
    const float* fsh  = (const float*)d_in[5];
    const int*   sel  = (const int*)d_in[6];
    const float* Wq = (const float*)d_in[7];
    const float* bq = (const float*)d_in[8];
    const float* Wk = (const float*)d_in[9];
    const float* bk = (const float*)d_in[10];
    const float* Wv = (const float*)d_in[11];
    const float* bv = (const float*)d_in[12];
    const float* Wo = (const float*)d_in[13];
    const float* bo = (const float*)d_in[14];
    const float* gq = (const float*)d_in[15];
    const float* gk = (const float*)d_in[16];
    float* outp = (float*)d_out;

    float *qp, *kp, *vp, *ap;
    cudaGetSymbolAddress((void**)&qp, g_q);
    cudaGetSymbolAddress((void**)&kp, g_k);
    cudaGetSymbolAddress((void**)&vp, g_v);
    cudaGetSymbolAddress((void**)&ap, g_attn);

    cudaFuncSetAttribute(gemm_bias_tf32,
                         cudaFuncAttributeMaxDynamicSharedMemorySize, GEMM_SMEM);
    cudaFuncSetAttribute(attention_kernel,
                         cudaFuncAttributeMaxDynamicSharedMemorySize, ATT_SMEM_WORDS * 4);

    gemm_bias_tf32<<<dim3(12, 25), 256, GEMM_SMEM>>>(hidden,  Wq, bq, qp, QTOT, DIM, DIM, nullptr);
    gemm_bias_tf32<<<dim3(12, 98), 256, GEMM_SMEM>>>(history, Wk, bk, kp, KTOT, DIM, DIM, sel);
    gemm_bias_tf32<<<dim3(12, 98), 256, GEMM_SMEM>>>(history, Wv, bv, vp, KTOT, DIM, DIM, sel);
    rmsnorm_rope_kernel<<<QTOT, 384>>>(qp, gq, fc, fs, nullptr);
    rmsnorm_rope_kernel<<<KTOT, 384>>>(kp, gk, fch, fsh, sel);
    attention_kernel<<<dim3(13, TQ, HEADS), 256, ATT_SMEM_WORDS * 4>>>(qp, kp, vp, sel, ap);
    gemm_bias_tf32<<<dim3(12, 25), 256, GEMM_SMEM>>>(ap, Wo, bo, outp, QTOT, DIM, DIM, nullptr);
}